// round 16
// baseline (speedup 1.0000x reference)
#include <cuda_runtime.h>
#include <cuda_fp16.h>
#include <mma.h>
#include <cstdint>

using namespace nvcuda;

#define BATCH 256
#define NSEQ  512
#define QDIM  2048
#define VDIM  2048
#define ADIM  1024
#define MROWS (BATCH * NSEQ)   // 131072

// ---- scratch (module-scope device arrays; no runtime allocation) ----
__device__ __half g_yh[(size_t)MROWS * VDIM];      // 512 MB, Y in fp16
__device__ __half g_wvh[(size_t)VDIM * ADIM];      // 4 MB, W_vis in fp16
__device__ __half g_xh[(size_t)BATCH * QDIM];      // 1 MB, X in fp16
__device__ __half g_wqh[(size_t)QDIM * ADIM];      // 4 MB, W_ques in fp16
__device__ float  g_x2att[BATCH * ADIM];           // 1 MB
__device__ float  g_part[8 * MROWS];               // 4 MB logit partials

// ======================= async-copy helpers =======================
__device__ __forceinline__ uint32_t smem_u32(const void* p) {
    uint32_t a;
    asm("{ .reg .u64 t; cvta.to.shared.u64 t, %1; cvt.u32.u64 %0, t; }" : "=r"(a) : "l"(p));
    return a;
}
__device__ __forceinline__ void cp16(uint32_t dst, const void* g) {
    asm volatile("cp.async.cg.shared.global [%0], [%1], 16;" :: "r"(dst), "l"(g));
}
#define CP_COMMIT() asm volatile("cp.async.commit_group;" ::: "memory")
#define CP_WAIT(n)  asm volatile("cp.async.wait_group %0;" :: "n"(n) : "memory")

// ======================= fp32 -> fp16 conversion passes =======================
__device__ __forceinline__ void cvt8(const float* __restrict__ src, __half* __restrict__ dst, size_t i)
{
    float4 v0 = *(const float4*)(src + i);
    float4 v1 = *(const float4*)(src + i + 4);
    __half2 h0 = __floats2half2_rn(v0.x, v0.y);
    __half2 h1 = __floats2half2_rn(v0.z, v0.w);
    __half2 h2 = __floats2half2_rn(v1.x, v1.y);
    __half2 h3 = __floats2half2_rn(v1.z, v1.w);
    uint4 packed;
    packed.x = *(uint32_t*)&h0; packed.y = *(uint32_t*)&h1;
    packed.z = *(uint32_t*)&h2; packed.w = *(uint32_t*)&h3;
    *(uint4*)(dst + i) = packed;
}

__global__ __launch_bounds__(256) void cvt_y(const float* __restrict__ Y)
{ cvt8(Y, g_yh, ((size_t)blockIdx.x * 256 + threadIdx.x) * 8); }

__global__ __launch_bounds__(256)
void cvt_small(const float* __restrict__ Wv, const float* __restrict__ X,
               const float* __restrict__ Wq)
{
    const size_t n1 = (size_t)VDIM * ADIM;
    const size_t n2 = n1 + (size_t)BATCH * QDIM;
    size_t i = ((size_t)blockIdx.x * 256 + threadIdx.x) * 8;
    if (i < n1)       cvt8(Wv, g_wvh, i);
    else if (i < n2)  cvt8(X,  g_xh,  i - n1);
    else              cvt8(Wq, g_wqh, i - n2);
}

// ======================= shared GEMM tiling constants =======================
constexpr int BM = 128, BN = 128, BK = 32;
constexpr int NK = QDIM / BK;                 // 64
constexpr int APH = 40;                       // A pitch in halves (80 B rows)
constexpr int BPH = 136;                      // B pitch in halves (272 B rows)
constexpr int A_BYTES = BM * APH * 2;         // 10240
constexpr int B_BYTES = BK * BPH * 2;         // 8704
constexpr int STAGE_BYTES = A_BYTES + B_BYTES;  // 18944
constexpr int EPI_P = BN + 4;
constexpr int STG = 6;                        // 6-slot ring, 2 stages per barrier
constexpr size_t DSMEM_GEMM = (size_t)STG * STAGE_BYTES;          // 113664
constexpr size_t DSMEM_EPI  = (size_t)BM * EPI_P * 4;             // 67584
constexpr size_t DSMEM = DSMEM_GEMM > DSMEM_EPI ? DSMEM_GEMM : DSMEM_EPI;

// ======================= fused logits GEMM (depth-2 barrier scheme) =======================
// part[nt, m] = sum_a relu( (Y @ W_vis)[m, a] + x2att[b(m), a] ) * W_map[a]
__global__ __launch_bounds__(256, 2)
void logits_mma(const float* __restrict__ Wmap)
{
    extern __shared__ char smc[];
    __shared__ float xs[BN], ws[BN];
    __shared__ float psum[BM][2];

    const int tid  = threadIdx.x;
    const int warp = tid >> 5;
    const int wr   = warp & 3;
    const int wc   = warp >> 2;

    const int ntile = blockIdx.x;       // 0..7 fastest (Y-tile L2 reuse)
    const int mtile = blockIdx.y;       // 0..1023
    const int a0    = ntile * BN;
    const size_t row0 = (size_t)mtile * BM;
    const int b     = mtile >> 2;

    const __half* Ab = g_yh + row0 * QDIM;
    const __half* Bb = g_wvh;
    const uint32_t sbase = smem_u32(smc);

    auto load_stage = [&](int st, int slot) {
        uint32_t base = sbase + (uint32_t)(slot * STAGE_BYTES);
        int k0 = st * BK;
        #pragma unroll
        for (int i = 0; i < 2; i++) {
            int idx = tid + i * 256;
            int r = idx >> 2, c = idx & 3;
            cp16(base + r * (APH * 2) + c * 16, Ab + (size_t)r * QDIM + k0 + c * 8);
        }
        #pragma unroll
        for (int i = 0; i < 2; i++) {
            int idx = tid + i * 256;
            int r = idx >> 4, c = idx & 15;
            cp16(base + A_BYTES + r * (BPH * 2) + c * 16,
                 Bb + (size_t)(k0 + r) * ADIM + a0 + c * 8);
        }
    };

    // one warp computing one kt-stage from a slot
    auto compute_stage = [&](const __half* sA, const __half* sB,
                             wmma::fragment<wmma::accumulator, 16, 16, 16, float> (&acc)[2][4]) {
        #pragma unroll
        for (int kk = 0; kk < BK; kk += 16) {
            wmma::fragment<wmma::matrix_a, 16, 16, 16, __half, wmma::row_major> af[2];
            wmma::fragment<wmma::matrix_b, 16, 16, 16, __half, wmma::row_major> bf[4];
            #pragma unroll
            for (int i = 0; i < 2; i++)
                wmma::load_matrix_sync(af[i], sA + (wr * 32 + i * 16) * APH + kk, APH);
            #pragma unroll
            for (int j = 0; j < 4; j++)
                wmma::load_matrix_sync(bf[j], sB + kk * BPH + wc * 64 + j * 16, BPH);
            #pragma unroll
            for (int i = 0; i < 2; i++)
                #pragma unroll
                for (int j = 0; j < 4; j++)
                    wmma::mma_sync(acc[i][j], af[i], bf[j], acc[i][j]);
        }
    };

    wmma::fragment<wmma::accumulator, 16, 16, 16, float> acc[2][4];
    #pragma unroll
    for (int i = 0; i < 2; i++)
        #pragma unroll
        for (int j = 0; j < 4; j++)
            wmma::fill_fragment(acc[i][j], 0.0f);

    // prologue: stages 0..3 into slots 0..3 (4 groups in flight)
    #pragma unroll
    for (int st = 0; st < 4; st++) { load_stage(st, st); CP_COMMIT(); }

    if (tid < BN) {
        xs[tid] = g_x2att[(size_t)b * ADIM + a0 + tid];
        ws[tid] = Wmap[a0 + tid];
    }

    int sc = 0;   // slot of stage kt (kt even): cycles 0 -> 2 -> 4 -> 0
    #pragma unroll 1
    for (int kt = 0; kt < NK; kt += 2) {
        CP_WAIT(2);              // stages kt, kt+1 resident (<=2 groups pending)
        __syncthreads();         // also fences prior compute on the reused slots

        // prefetch stages kt+4, kt+5 into slots used 2 stages ago
        int ld0 = (sc >= 2) ? sc - 2 : sc + 4;   // (sc+4) % 6
        if (kt + 4 < NK) load_stage(kt + 4, ld0);
        CP_COMMIT();
        if (kt + 5 < NK) load_stage(kt + 5, ld0 + 1);
        CP_COMMIT();

        const char* s0 = smc + sc * STAGE_BYTES;
        const char* s1 = smc + (sc + 1) * STAGE_BYTES;
        compute_stage((const __half*)s0, (const __half*)(s0 + A_BYTES), acc);
        compute_stage((const __half*)s1, (const __half*)(s1 + A_BYTES), acc);

        sc = (sc == 4) ? 0 : sc + 2;
    }

    __syncthreads();

    float* Epi = (float*)smc;
    #pragma unroll
    for (int i = 0; i < 2; i++)
        #pragma unroll
        for (int j = 0; j < 4; j++)
            wmma::store_matrix_sync(Epi + (wr * 32 + i * 16) * EPI_P + wc * 64 + j * 16,
                                    acc[i][j], EPI_P, wmma::mem_row_major);
    __syncthreads();

    const int r = tid & 127;
    const int half = tid >> 7;
    const float* er = Epi + r * EPI_P + half * 64;
    float s = 0.0f;
    #pragma unroll 8
    for (int j = 0; j < 64; j++) {
        int c = half * 64 + j;
        float v = er[j] + xs[c];
        s += fmaxf(v, 0.0f) * ws[c];
    }
    psum[r][half] = s;
    __syncthreads();
    if (tid < BM)
        g_part[(size_t)ntile * MROWS + row0 + tid] = psum[tid][0] + psum[tid][1];
}

// ======================= X2att = X @ W_ques + b_ques (fp16, R12-proven) =======================
constexpr size_t XDSMEM_G = (size_t)4 * STAGE_BYTES;             // 75776
constexpr size_t XDSMEM_E = (size_t)BM * EPI_P * 4;              // 67584
constexpr size_t XDSMEM = XDSMEM_G > XDSMEM_E ? XDSMEM_G : XDSMEM_E;

__global__ __launch_bounds__(256, 2)
void x2att_mma(const float* __restrict__ bias)
{
    extern __shared__ char smc[];

    const int tid  = threadIdx.x;
    const int warp = tid >> 5;
    const int wr   = warp & 3;
    const int wc   = warp >> 2;

    const int a0   = blockIdx.x * BN;
    const size_t row0 = (size_t)blockIdx.y * BM;

    const __half* Ab = g_xh + row0 * QDIM;
    const __half* Bb = g_wqh;
    const uint32_t sbase = smem_u32(smc);

    auto load_stage = [&](int st) {
        uint32_t base = sbase + (uint32_t)((st & 3) * STAGE_BYTES);
        int k0 = st * BK;
        #pragma unroll
        for (int i = 0; i < 2; i++) {
            int idx = tid + i * 256;
            int r = idx >> 2, c = idx & 3;
            cp16(base + r * (APH * 2) + c * 16, Ab + (size_t)r * QDIM + k0 + c * 8);
        }
        #pragma unroll
        for (int i = 0; i < 2; i++) {
            int idx = tid + i * 256;
            int r = idx >> 4, c = idx & 15;
            cp16(base + A_BYTES + r * (BPH * 2) + c * 16,
                 Bb + (size_t)(k0 + r) * ADIM + a0 + c * 8);
        }
    };

    wmma::fragment<wmma::accumulator, 16, 16, 16, float> acc[2][4];
    #pragma unroll
    for (int i = 0; i < 2; i++)
        #pragma unroll
        for (int j = 0; j < 4; j++)
            wmma::fill_fragment(acc[i][j], 0.0f);

    load_stage(0); CP_COMMIT();
    load_stage(1); CP_COMMIT();
    load_stage(2); CP_COMMIT();

    #pragma unroll 1
    for (int kt = 0; kt < NK; kt++) {
        CP_WAIT(2);
        __syncthreads();

        if (kt + 3 < NK) load_stage(kt + 3);
        CP_COMMIT();

        const __half* sA = (const __half*)(smc + (kt & 3) * STAGE_BYTES);
        const __half* sB = (const __half*)(smc + (kt & 3) * STAGE_BYTES + A_BYTES);

        #pragma unroll
        for (int kk = 0; kk < BK; kk += 16) {
            wmma::fragment<wmma::matrix_a, 16, 16, 16, __half, wmma::row_major> af[2];
            wmma::fragment<wmma::matrix_b, 16, 16, 16, __half, wmma::row_major> bf[4];
            #pragma unroll
            for (int i = 0; i < 2; i++)
                wmma::load_matrix_sync(af[i], sA + (wr * 32 + i * 16) * APH + kk, APH);
            #pragma unroll
            for (int j = 0; j < 4; j++)
                wmma::load_matrix_sync(bf[j], sB + kk * BPH + wc * 64 + j * 16, BPH);
            #pragma unroll
            for (int i = 0; i < 2; i++)
                #pragma unroll
                for (int j = 0; j < 4; j++)
                    wmma::mma_sync(acc[i][j], af[i], bf[j], acc[i][j]);
        }
    }

    __syncthreads();

    float* Epi = (float*)smc;
    #pragma unroll
    for (int i = 0; i < 2; i++)
        #pragma unroll
        for (int j = 0; j < 4; j++)
            wmma::store_matrix_sync(Epi + (wr * 32 + i * 16) * EPI_P + wc * 64 + j * 16,
                                    acc[i][j], EPI_P, wmma::mem_row_major);
    __syncthreads();

    for (int e = tid; e < BM * BN; e += 256) {
        int r = e >> 7, c = e & 127;
        g_x2att[(row0 + r) * ADIM + a0 + c] = Epi[r * EPI_P + c] + bias[a0 + c];
    }
}

// ======================= fused softmax + attend (one block per batch) =======================
__global__ __launch_bounds__(256)
void attend_k(float* __restrict__ out)
{
    __shared__ float w[NSEQ];
    __shared__ float red[256];
    const int b = blockIdx.x;
    const int t = threadIdx.x;

    float v0 = 0.0f, v1 = 0.0f;
    #pragma unroll
    for (int p = 0; p < 8; p++) {
        const float* P = g_part + (size_t)p * MROWS + (size_t)b * NSEQ;
        v0 += P[t]; v1 += P[t + 256];
    }
    red[t] = fmaxf(v0, v1);
    __syncthreads();
    for (int s = 128; s > 0; s >>= 1) { if (t < s) red[t] = fmaxf(red[t], red[t + s]); __syncthreads(); }
    float m = red[0];
    __syncthreads();
    float e0 = __expf(v0 - m), e1 = __expf(v1 - m);
    red[t] = e0 + e1;
    __syncthreads();
    for (int s = 128; s > 0; s >>= 1) { if (t < s) red[t] += red[t + s]; __syncthreads(); }
    float inv = 1.0f / red[0];
    w[t]       = e0 * inv;
    w[t + 256] = e1 * inv;
    __syncthreads();

    const __half* Yb = g_yh + (size_t)b * NSEQ * VDIM + t * 8;
    float acc[8] = {0.f};
    #pragma unroll 4
    for (int n = 0; n < NSEQ; n++) {
        uint4 p = *(const uint4*)(Yb + (size_t)n * VDIM);
        float wn = w[n];
        float2 f0 = __half22float2(*(__half2*)&p.x);
        float2 f1 = __half22float2(*(__half2*)&p.y);
        float2 f2 = __half22float2(*(__half2*)&p.z);
        float2 f3 = __half22float2(*(__half2*)&p.w);
        acc[0] += wn * f0.x; acc[1] += wn * f0.y;
        acc[2] += wn * f1.x; acc[3] += wn * f1.y;
        acc[4] += wn * f2.x; acc[5] += wn * f2.y;
        acc[6] += wn * f3.x; acc[7] += wn * f3.y;
    }
    float4 o0 = make_float4(acc[0], acc[1], acc[2], acc[3]);
    float4 o1 = make_float4(acc[4], acc[5], acc[6], acc[7]);
    *(float4*)(out + (size_t)b * VDIM + t * 8)     = o0;
    *(float4*)(out + (size_t)b * VDIM + t * 8 + 4) = o1;
}

// ======================= launch =======================
extern "C" void kernel_launch(void* const* d_in, const int* in_sizes, int n_in,
                              void* d_out, int out_size)
{
    const float* X      = (const float*)d_in[0];
    const float* Y      = (const float*)d_in[1];
    const float* W_vis  = (const float*)d_in[2];
    const float* W_ques = (const float*)d_in[3];
    const float* b_ques = (const float*)d_in[4];
    const float* W_map  = (const float*)d_in[5];
    // d_in[6] = b_map: cancels under softmax shift-invariance.
    float* out = (float*)d_out;

    cudaFuncSetAttribute(x2att_mma,  cudaFuncAttributeMaxDynamicSharedMemorySize, (int)XDSMEM);
    cudaFuncSetAttribute(logits_mma, cudaFuncAttributeMaxDynamicSharedMemorySize, (int)DSMEM);

    const size_t small_total = (size_t)VDIM * ADIM + (size_t)BATCH * QDIM + (size_t)QDIM * ADIM;
    cvt_y    <<<(size_t)MROWS * VDIM / (256 * 8), 256>>>(Y);
    cvt_small<<<small_total / (256 * 8), 256>>>(W_vis, X, W_ques);
    x2att_mma<<<dim3(ADIM / BN, BATCH / BM), 256, XDSMEM>>>(b_ques);
    logits_mma<<<dim3(ADIM / BN, MROWS / BM), 256, DSMEM>>>(W_map);
    attend_k<<<BATCH, 256>>>(out);
}

// round 17
// speedup vs baseline: 1.0576x; 1.0576x over previous
#include <cuda_runtime.h>
#include <cuda_fp16.h>
#include <mma.h>
#include <cstdint>

using namespace nvcuda;

#define BATCH 256
#define NSEQ  512
#define QDIM  2048
#define VDIM  2048
#define ADIM  1024
#define MROWS (BATCH * NSEQ)   // 131072

// ---- scratch (module-scope device arrays; no runtime allocation) ----
__device__ __half g_yh[(size_t)MROWS * VDIM];      // 512 MB, Y in fp16
__device__ __half g_wvh[(size_t)VDIM * ADIM];      // 4 MB, W_vis in fp16
__device__ __half g_xh[(size_t)BATCH * QDIM];      // 1 MB, X in fp16
__device__ __half g_wqh[(size_t)QDIM * ADIM];      // 4 MB, W_ques in fp16
__device__ float  g_x2att[BATCH * ADIM];           // 1 MB
__device__ float  g_part[8 * MROWS];               // 4 MB logit partials

// ======================= async-copy helpers =======================
__device__ __forceinline__ uint32_t smem_u32(const void* p) {
    uint32_t a;
    asm("{ .reg .u64 t; cvta.to.shared.u64 t, %1; cvt.u32.u64 %0, t; }" : "=r"(a) : "l"(p));
    return a;
}
__device__ __forceinline__ void cp16(uint32_t dst, const void* g) {
    asm volatile("cp.async.cg.shared.global [%0], [%1], 16;" :: "r"(dst), "l"(g));
}
#define CP_COMMIT() asm volatile("cp.async.commit_group;" ::: "memory")
#define CP_WAIT(n)  asm volatile("cp.async.wait_group %0;" :: "n"(n) : "memory")

// ======================= fp32 -> fp16 conversion (single kernel, all tensors) =======================
__device__ __forceinline__ void cvt8(const float* __restrict__ src, __half* __restrict__ dst, size_t i)
{
    float4 v0 = *(const float4*)(src + i);
    float4 v1 = *(const float4*)(src + i + 4);
    __half2 h0 = __floats2half2_rn(v0.x, v0.y);
    __half2 h1 = __floats2half2_rn(v0.z, v0.w);
    __half2 h2 = __floats2half2_rn(v1.x, v1.y);
    __half2 h3 = __floats2half2_rn(v1.z, v1.w);
    uint4 packed;
    packed.x = *(uint32_t*)&h0; packed.y = *(uint32_t*)&h1;
    packed.z = *(uint32_t*)&h2; packed.w = *(uint32_t*)&h3;
    *(uint4*)(dst + i) = packed;
}

constexpr size_t CVT_NY = (size_t)MROWS * VDIM;                 // 268435456
constexpr size_t CVT_N1 = CVT_NY + (size_t)VDIM * ADIM;         // + 2097152
constexpr size_t CVT_N2 = CVT_N1 + (size_t)BATCH * QDIM;        // + 524288
constexpr size_t CVT_N3 = CVT_N2 + (size_t)QDIM * ADIM;         // + 2097152 (total)

__global__ __launch_bounds__(256)
void cvt_all(const float* __restrict__ Y,  const float* __restrict__ Wv,
             const float* __restrict__ X,  const float* __restrict__ Wq)
{
    size_t i = ((size_t)blockIdx.x * 256 + threadIdx.x) * 8;
    if (i < CVT_NY)        cvt8(Y,  g_yh,  i);
    else if (i < CVT_N1)   cvt8(Wv, g_wvh, i - CVT_NY);
    else if (i < CVT_N2)   cvt8(X,  g_xh,  i - CVT_N1);
    else                   cvt8(Wq, g_wqh, i - CVT_N2);
}

// ======================= shared GEMM tiling constants (R13-proven) =======================
constexpr int BM = 128, BN = 128, BK = 32;
constexpr int NK = QDIM / BK;                 // 64
constexpr int APH = 40;                       // A pitch in halves (80 B rows)
constexpr int BPH = 136;                      // B pitch in halves (272 B rows)
constexpr int A_BYTES = BM * APH * 2;         // 10240
constexpr int B_BYTES = BK * BPH * 2;         // 8704
constexpr int STAGE_BYTES = A_BYTES + B_BYTES;  // 18944
constexpr int EPI_P = BN + 4;
constexpr size_t DSMEM_GEMM = (size_t)4 * STAGE_BYTES;            // 75776
constexpr size_t DSMEM_EPI  = (size_t)BM * EPI_P * 4;             // 67584
constexpr size_t DSMEM = DSMEM_GEMM > DSMEM_EPI ? DSMEM_GEMM : DSMEM_EPI;

// ======================= fused logits GEMM (R13-proven, unchanged) =======================
// part[nt, m] = sum_a relu( (Y @ W_vis)[m, a] + x2att[b(m), a] ) * W_map[a]
__global__ __launch_bounds__(256, 2)
void logits_mma(const float* __restrict__ Wmap)
{
    extern __shared__ char smc[];
    __shared__ float xs[BN], ws[BN];
    __shared__ float psum[BM][2];

    const int tid  = threadIdx.x;
    const int warp = tid >> 5;
    const int wr   = warp & 3;
    const int wc   = warp >> 2;

    const int ntile = blockIdx.x;       // 0..7 fastest (Y-tile L2 reuse)
    const int mtile = blockIdx.y;       // 0..1023
    const int a0    = ntile * BN;
    const size_t row0 = (size_t)mtile * BM;
    const int b     = mtile >> 2;

    if (tid < BN) {
        xs[tid] = g_x2att[(size_t)b * ADIM + a0 + tid];
        ws[tid] = Wmap[a0 + tid];
    }

    const __half* Ab = g_yh + row0 * QDIM;
    const __half* Bb = g_wvh;
    const uint32_t sbase = smem_u32(smc);

    auto load_stage = [&](int st) {
        uint32_t base = sbase + (uint32_t)((st & 3) * STAGE_BYTES);
        int k0 = st * BK;
        #pragma unroll
        for (int i = 0; i < 2; i++) {
            int idx = tid + i * 256;
            int r = idx >> 2, c = idx & 3;
            cp16(base + r * (APH * 2) + c * 16, Ab + (size_t)r * QDIM + k0 + c * 8);
        }
        #pragma unroll
        for (int i = 0; i < 2; i++) {
            int idx = tid + i * 256;
            int r = idx >> 4, c = idx & 15;
            cp16(base + A_BYTES + r * (BPH * 2) + c * 16,
                 Bb + (size_t)(k0 + r) * ADIM + a0 + c * 8);
        }
    };

    wmma::fragment<wmma::accumulator, 16, 16, 16, float> acc[2][4];
    #pragma unroll
    for (int i = 0; i < 2; i++)
        #pragma unroll
        for (int j = 0; j < 4; j++)
            wmma::fill_fragment(acc[i][j], 0.0f);

    load_stage(0); CP_COMMIT();
    load_stage(1); CP_COMMIT();
    load_stage(2); CP_COMMIT();

    #pragma unroll 1
    for (int kt = 0; kt < NK; kt++) {
        CP_WAIT(2);
        __syncthreads();

        if (kt + 3 < NK) load_stage(kt + 3);
        CP_COMMIT();

        const __half* sA = (const __half*)(smc + (kt & 3) * STAGE_BYTES);
        const __half* sB = (const __half*)(smc + (kt & 3) * STAGE_BYTES + A_BYTES);

        #pragma unroll
        for (int kk = 0; kk < BK; kk += 16) {
            wmma::fragment<wmma::matrix_a, 16, 16, 16, __half, wmma::row_major> af[2];
            wmma::fragment<wmma::matrix_b, 16, 16, 16, __half, wmma::row_major> bf[4];
            #pragma unroll
            for (int i = 0; i < 2; i++)
                wmma::load_matrix_sync(af[i], sA + (wr * 32 + i * 16) * APH + kk, APH);
            #pragma unroll
            for (int j = 0; j < 4; j++)
                wmma::load_matrix_sync(bf[j], sB + kk * BPH + wc * 64 + j * 16, BPH);
            #pragma unroll
            for (int i = 0; i < 2; i++)
                #pragma unroll
                for (int j = 0; j < 4; j++)
                    wmma::mma_sync(acc[i][j], af[i], bf[j], acc[i][j]);
        }
    }

    __syncthreads();

    float* Epi = (float*)smc;
    #pragma unroll
    for (int i = 0; i < 2; i++)
        #pragma unroll
        for (int j = 0; j < 4; j++)
            wmma::store_matrix_sync(Epi + (wr * 32 + i * 16) * EPI_P + wc * 64 + j * 16,
                                    acc[i][j], EPI_P, wmma::mem_row_major);
    __syncthreads();

    const int r = tid & 127;
    const int half = tid >> 7;
    const float* er = Epi + r * EPI_P + half * 64;
    float s = 0.0f;
    #pragma unroll 8
    for (int j = 0; j < 64; j++) {
        int c = half * 64 + j;
        float v = er[j] + xs[c];
        s += fmaxf(v, 0.0f) * ws[c];
    }
    psum[r][half] = s;
    __syncthreads();
    if (tid < BM)
        g_part[(size_t)ntile * MROWS + row0 + tid] = psum[tid][0] + psum[tid][1];
}

// ======================= X2att = X @ W_ques + b_ques (fp16, R12-proven) =======================
__global__ __launch_bounds__(256, 2)
void x2att_mma(const float* __restrict__ bias)
{
    extern __shared__ char smc[];

    const int tid  = threadIdx.x;
    const int warp = tid >> 5;
    const int wr   = warp & 3;
    const int wc   = warp >> 2;

    const int a0   = blockIdx.x * BN;
    const size_t row0 = (size_t)blockIdx.y * BM;

    const __half* Ab = g_xh + row0 * QDIM;
    const __half* Bb = g_wqh;
    const uint32_t sbase = smem_u32(smc);

    auto load_stage = [&](int st) {
        uint32_t base = sbase + (uint32_t)((st & 3) * STAGE_BYTES);
        int k0 = st * BK;
        #pragma unroll
        for (int i = 0; i < 2; i++) {
            int idx = tid + i * 256;
            int r = idx >> 2, c = idx & 3;
            cp16(base + r * (APH * 2) + c * 16, Ab + (size_t)r * QDIM + k0 + c * 8);
        }
        #pragma unroll
        for (int i = 0; i < 2; i++) {
            int idx = tid + i * 256;
            int r = idx >> 4, c = idx & 15;
            cp16(base + A_BYTES + r * (BPH * 2) + c * 16,
                 Bb + (size_t)(k0 + r) * ADIM + a0 + c * 8);
        }
    };

    wmma::fragment<wmma::accumulator, 16, 16, 16, float> acc[2][4];
    #pragma unroll
    for (int i = 0; i < 2; i++)
        #pragma unroll
        for (int j = 0; j < 4; j++)
            wmma::fill_fragment(acc[i][j], 0.0f);

    load_stage(0); CP_COMMIT();
    load_stage(1); CP_COMMIT();
    load_stage(2); CP_COMMIT();

    #pragma unroll 1
    for (int kt = 0; kt < NK; kt++) {
        CP_WAIT(2);
        __syncthreads();

        if (kt + 3 < NK) load_stage(kt + 3);
        CP_COMMIT();

        const __half* sA = (const __half*)(smc + (kt & 3) * STAGE_BYTES);
        const __half* sB = (const __half*)(smc + (kt & 3) * STAGE_BYTES + A_BYTES);

        #pragma unroll
        for (int kk = 0; kk < BK; kk += 16) {
            wmma::fragment<wmma::matrix_a, 16, 16, 16, __half, wmma::row_major> af[2];
            wmma::fragment<wmma::matrix_b, 16, 16, 16, __half, wmma::row_major> bf[4];
            #pragma unroll
            for (int i = 0; i < 2; i++)
                wmma::load_matrix_sync(af[i], sA + (wr * 32 + i * 16) * APH + kk, APH);
            #pragma unroll
            for (int j = 0; j < 4; j++)
                wmma::load_matrix_sync(bf[j], sB + kk * BPH + wc * 64 + j * 16, BPH);
            #pragma unroll
            for (int i = 0; i < 2; i++)
                #pragma unroll
                for (int j = 0; j < 4; j++)
                    wmma::mma_sync(acc[i][j], af[i], bf[j], acc[i][j]);
        }
    }

    __syncthreads();

    float* Epi = (float*)smc;
    #pragma unroll
    for (int i = 0; i < 2; i++)
        #pragma unroll
        for (int j = 0; j < 4; j++)
            wmma::store_matrix_sync(Epi + (wr * 32 + i * 16) * EPI_P + wc * 64 + j * 16,
                                    acc[i][j], EPI_P, wmma::mem_row_major);
    __syncthreads();

    for (int e = tid; e < BM * BN; e += 256) {
        int r = e >> 7, c = e & 127;
        g_x2att[(row0 + r) * ADIM + a0 + c] = Epi[r * EPI_P + c] + bias[a0 + c];
    }
}

// ======================= fused softmax + attend (one block per batch) =======================
__global__ __launch_bounds__(256)
void attend_k(float* __restrict__ out)
{
    __shared__ float w[NSEQ];
    __shared__ float red[256];
    const int b = blockIdx.x;
    const int t = threadIdx.x;

    float v0 = 0.0f, v1 = 0.0f;
    #pragma unroll
    for (int p = 0; p < 8; p++) {
        const float* P = g_part + (size_t)p * MROWS + (size_t)b * NSEQ;
        v0 += P[t]; v1 += P[t + 256];
    }
    red[t] = fmaxf(v0, v1);
    __syncthreads();
    for (int s = 128; s > 0; s >>= 1) { if (t < s) red[t] = fmaxf(red[t], red[t + s]); __syncthreads(); }
    float m = red[0];
    __syncthreads();
    float e0 = __expf(v0 - m), e1 = __expf(v1 - m);
    red[t] = e0 + e1;
    __syncthreads();
    for (int s = 128; s > 0; s >>= 1) { if (t < s) red[t] += red[t + s]; __syncthreads(); }
    float inv = 1.0f / red[0];
    w[t]       = e0 * inv;
    w[t + 256] = e1 * inv;
    __syncthreads();

    const __half* Yb = g_yh + (size_t)b * NSEQ * VDIM + t * 8;
    float acc[8] = {0.f};
    #pragma unroll 4
    for (int n = 0; n < NSEQ; n++) {
        uint4 p = *(const uint4*)(Yb + (size_t)n * VDIM);
        float wn = w[n];
        float2 f0 = __half22float2(*(__half2*)&p.x);
        float2 f1 = __half22float2(*(__half2*)&p.y);
        float2 f2 = __half22float2(*(__half2*)&p.z);
        float2 f3 = __half22float2(*(__half2*)&p.w);
        acc[0] += wn * f0.x; acc[1] += wn * f0.y;
        acc[2] += wn * f1.x; acc[3] += wn * f1.y;
        acc[4] += wn * f2.x; acc[5] += wn * f2.y;
        acc[6] += wn * f3.x; acc[7] += wn * f3.y;
    }
    float4 o0 = make_float4(acc[0], acc[1], acc[2], acc[3]);
    float4 o1 = make_float4(acc[4], acc[5], acc[6], acc[7]);
    *(float4*)(out + (size_t)b * VDIM + t * 8)     = o0;
    *(float4*)(out + (size_t)b * VDIM + t * 8 + 4) = o1;
}

// ======================= launch =======================
extern "C" void kernel_launch(void* const* d_in, const int* in_sizes, int n_in,
                              void* d_out, int out_size)
{
    const float* X      = (const float*)d_in[0];
    const float* Y      = (const float*)d_in[1];
    const float* W_vis  = (const float*)d_in[2];
    const float* W_ques = (const float*)d_in[3];
    const float* b_ques = (const float*)d_in[4];
    const float* W_map  = (const float*)d_in[5];
    // d_in[6] = b_map: cancels under softmax shift-invariance.
    float* out = (float*)d_out;

    cudaFuncSetAttribute(x2att_mma,  cudaFuncAttributeMaxDynamicSharedMemorySize, (int)DSMEM);
    cudaFuncSetAttribute(logits_mma, cudaFuncAttributeMaxDynamicSharedMemorySize, (int)DSMEM);

    cvt_all<<<CVT_N3 / (256 * 8), 256>>>(Y, W_vis, X, W_ques);
    x2att_mma<<<dim3(ADIM / BN, BATCH / BM), 256, DSMEM>>>(b_ques);
    logits_mma<<<dim3(ADIM / BN, MROWS / BM), 256, DSMEM>>>(W_map);
    attend_k<<<BATCH, 256>>>(out);
}